// round 10
// baseline (speedup 1.0000x reference)
#include <cuda_runtime.h>

// x: (2,8,4,256,384) fp32 -> 16 independent DxHxW volumes
#define WD   384
#define HT   256
#define DP   4
#define HW   (HT*WD)          // 98304
#define DHW  (DP*HW)          // 393216
#define NIMG 16

#define OUTW   30             // output columns per warp strip (lanes 1..30)
#define NSTRIP 13             // ceil(384/30)
#define CH     8              // output rows per h-chunk
#define NCH    (HT/CH)        // 32
#define WPB    4              // warps per block
#define HALF_TASKS (NSTRIP*NCH*NIMG)   // 6656 warp-tasks per depth-half
#define NTASK  (2*HALF_TASKS)          // 13312

#define BONUS 10.0f
#define FULL  0xffffffffu

typedef unsigned long long u64;

// ---- packed f32x2 primitives (Blackwell) ----
__device__ __forceinline__ u64 pk2(float lo, float hi) {
    u64 r; asm("mov.b64 %0, {%1, %2};" : "=l"(r) : "f"(lo), "f"(hi)); return r;
}
__device__ __forceinline__ void upk2(u64 v, float& lo, float& hi) {
    asm("mov.b64 {%0, %1}, %2;" : "=f"(lo), "=f"(hi) : "l"(v));
}
__device__ __forceinline__ u64 f2add(u64 a, u64 b) {
    u64 r; asm("add.rn.f32x2 %0, %1, %2;" : "=l"(r) : "l"(a), "l"(b)); return r;
}
__device__ __forceinline__ u64 f2mul(u64 a, u64 b) {
    u64 r; asm("mul.rn.f32x2 %0, %1, %2;" : "=l"(r) : "l"(a), "l"(b)); return r;
}
__device__ __forceinline__ u64 f2fma(u64 a, u64 b, u64 c) {
    u64 r; asm("fma.rn.f32x2 %0, %1, %2, %3;" : "=l"(r) : "l"(a), "l"(b), "l"(c)); return r;
}
#define F2_NEG1  0xBF800000BF800000ULL
#define F2_NEG2  0xC0000000C0000000ULL
#define F2_HALF  0x3F0000003F000000ULL
#define F2_QUART 0x3E8000003E800000ULL
// sub(a,b) = fma(b, -1, a)
#define F2SUB(a,b) f2fma((b), F2_NEG1, (a))

// Per depth-half local plane maps (local planes 0..2):
// DHALF=0 -> global planes {0,1,2}, depths {0,1}: PM={0,1} PA={0,0} PC={1,2}
// DHALF=1 -> global planes {1,2,3}, depths {2,3}: PM={1,2} PA={0,1} PC={2,2}

template<int DHALF>
__device__ __forceinline__ void run_half(const float* __restrict__ xg,
                                         float* __restrict__ out,
                                         int task, int lane)
{
    constexpr int PM0 = DHALF ? 1 : 0, PM1 = DHALF ? 2 : 1;
    constexpr int PA0 = DHALF ? 0 : 0, PA1 = DHALF ? 1 : 0;
    constexpr int PC0 = DHALF ? 2 : 1, PC1 = DHALF ? 2 : 2;

    const int img   = task / (NSTRIP * NCH);
    const int rem   = task - img * (NSTRIP * NCH);
    const int strip = rem % NSTRIP;
    const int hc    = rem / NSTRIP;

    const int w0   = strip * OUTW;
    const int wout = w0 + lane - 1;
    const bool active = (lane >= 1) && (lane <= 30) && (wout < WD);
    int wcol = wout; if (wcol < 0) wcol = 0; if (wcol > WD-1) wcol = WD-1;

    const int h0 = hc * CH;
    const float wf  = (float)wout;
    const float df0 = (float)(DHALF * 2);
    const float df1 = df0 + 1.0f;

    const float* __restrict__ xin = xg + (size_t)img * DHW + DHALF * HW + wcol;

    // 3-slot rolling row window over 3 local planes
    float val[3][3], lf[3][3], rg[3][3], wm[3][2];
    float pend[3];

    #define LOADROW(HR, DST)                                             \
        do {                                                             \
            const float* _p = xin + (HR) * WD;                           \
            (DST)[0] = __ldg(_p);                                        \
            (DST)[1] = __ldg(_p + HW);                                   \
            (DST)[2] = __ldg(_p + 2*HW);                                 \
        } while (0)

    #define COMMIT(RAW, S)                                               \
        do {                                                             \
            _Pragma("unroll")                                            \
            for (int p = 0; p < 3; ++p) {                                \
                float _v = (RAW)[p];                                     \
                val[S][p] = _v;                                          \
                lf[S][p]  = __shfl_up_sync(FULL, _v, 1);                 \
                rg[S][p]  = __shfl_down_sync(FULL, _v, 1);               \
            }                                                            \
            float _h0 = fmaxf(fmaxf(lf[S][0], val[S][0]), rg[S][0]);     \
            float _h1 = fmaxf(fmaxf(lf[S][1], val[S][1]), rg[S][1]);     \
            float _h2 = fmaxf(fmaxf(lf[S][2], val[S][2]), rg[S][2]);     \
            float _hA0 = (PA0==0?_h0:(PA0==1?_h1:_h2));                  \
            float _hM0 = (PM0==0?_h0:(PM0==1?_h1:_h2));                  \
            float _hC0 = (PC0==0?_h0:(PC0==1?_h1:_h2));                  \
            float _hA1 = (PA1==0?_h0:(PA1==1?_h1:_h2));                  \
            float _hM1 = (PM1==0?_h0:(PM1==1?_h1:_h2));                  \
            float _hC1 = (PC1==0?_h0:(PC1==1?_h1:_h2));                  \
            wm[S][0] = fmaxf(fmaxf(_hA0, _hM0), _hC0);                   \
            wm[S][1] = fmaxf(fmaxf(_hA1, _hM1), _hC1);                   \
        } while (0)

    // ---- prologue ----
    {
        float ra[3], rb[3];
        int r_up = h0 - 1; if (r_up < 0) r_up = 0;
        LOADROW(r_up, ra);
        LOADROW(h0,  rb);
        COMMIT(ra, 0);
        COMMIT(rb, 1);
        int r_dn = h0 + 1; if (r_dn > HT-1) r_dn = HT-1;
        LOADROW(r_dn, pend);
    }

    float* __restrict__ oc0 = out + (size_t)img * 3 * DHW;
    float* __restrict__ oy  = out + (size_t)NIMG * 3 * DHW + (size_t)img * DHW;

    int obase = h0 * WD + wout;

    #pragma unroll
    for (int i = 0; i < CH; ++i) {
        const int h  = h0 + i;
        const int sU = i % 3;
        const int sM = (i + 1) % 3;
        const int sD = (i + 2) % 3;
        const float hf = (float)h;

        float tmp[3];
        #pragma unroll
        for (int p = 0; p < 3; ++p) tmp[p] = pend[p];
        int rn = h + 2; if (rn > HT-1) rn = HT-1;
        LOADROW(rn, pend);
        COMMIT(tmp, sD);

        const float xc0 = val[sM][PM0];
        const float xc1 = val[sM][PM1];
        const float mx0 = fmaxf(fmaxf(wm[sU][0], wm[sM][0]), wm[sD][0]);
        const float mx1 = fmaxf(fmaxf(wm[sU][1], wm[sM][1]), wm[sD][1]);
        const bool nms0 = (xc0 == mx0);
        const bool nms1 = (xc1 == mx1);
        const int o0 = obase + (DHALF*2) * HW;
        const int o1 = o0 + HW;

        // pair-level warp-uniform fast path: no NMS max for either depth
        const unsigned bal = __ballot_sync(FULL, (nms0 | nms1) && active);
        if (bal == 0u) {
            if (active) {
                oc0[o0 + 0*DHW] = df0;  oc0[o1 + 0*DHW] = df1;
                oc0[o0 + 1*DHW] = wf;   oc0[o1 + 1*DHW] = wf;
                oc0[o0 + 2*DHW] = hf;   oc0[o1 + 2*DHW] = hf;
                oy [o0]         = xc0;  oy [o1]         = xc1;
            }
        } else {
            // ---- packed f32x2 solve for both depths ----
            const u64 vM  = pk2(xc0, xc1);
            const u64 lM  = pk2(lf[sM][PM0],  lf[sM][PM1]);
            const u64 rM  = pk2(rg[sM][PM0],  rg[sM][PM1]);
            const u64 vU  = pk2(val[sU][PM0], val[sU][PM1]);
            const u64 vD  = pk2(val[sD][PM0], val[sD][PM1]);
            const u64 vMa = pk2(val[sM][PA0], val[sM][PA1]);
            const u64 vMc = pk2(val[sM][PC0], val[sM][PC1]);
            const u64 lU  = pk2(lf[sU][PM0],  lf[sU][PM1]);
            const u64 rU  = pk2(rg[sU][PM0],  rg[sU][PM1]);
            const u64 lD  = pk2(lf[sD][PM0],  lf[sD][PM1]);
            const u64 rD  = pk2(rg[sD][PM0],  rg[sD][PM1]);
            const u64 vUa = pk2(val[sU][PA0], val[sU][PA1]);
            const u64 vDa = pk2(val[sD][PA0], val[sD][PA1]);
            const u64 vUc = pk2(val[sU][PC0], val[sU][PC1]);
            const u64 vDc = pk2(val[sD][PC0], val[sD][PC1]);
            const u64 lMa = pk2(lf[sM][PA0],  lf[sM][PA1]);
            const u64 rMa = pk2(rg[sM][PA0],  rg[sM][PA1]);
            const u64 lMc = pk2(lf[sM][PC0],  lf[sM][PC1]);
            const u64 rMc = pk2(rg[sM][PC0],  rg[sM][PC1]);

            const u64 b0 = f2mul(F2SUB(rM, lM), F2_HALF);   // dx
            const u64 b1 = f2mul(F2SUB(vD, vU), F2_HALF);   // dy
            const u64 b2 = f2mul(F2SUB(vMa, vMc), F2_HALF); // ds (flipped)

            const u64 dxx = f2fma(vM, F2_NEG2, f2add(rM, lM));
            const u64 dyy = f2fma(vM, F2_NEG2, f2add(vD, vU));
            const u64 dss = f2fma(vM, F2_NEG2, f2add(vMc, vMa));
            //  lU - rU - lD + rD
            const u64 dxy = f2mul(f2add(F2SUB(lU, rU), F2SUB(rD, lD)), F2_QUART);
            // -vUa + vDa + vUc - vDc
            const u64 dys = f2mul(f2add(F2SUB(vDa, vUa), F2SUB(vUc, vDc)), F2_QUART);
            // -lMa + rMa + lMc - rMc
            const u64 dxs = f2mul(f2add(F2SUB(rMa, lMa), F2SUB(lMc, rMc)), F2_QUART);

            const u64 ndys = f2mul(dys, F2_NEG1);
            const u64 ndxy = f2mul(dxy, F2_NEG1);
            const u64 ndxs = f2mul(dxs, F2_NEG1);
            const u64 c00 = f2fma(dyy, dss, f2mul(ndys, dys));
            const u64 c01 = f2fma(dxs, dys, f2mul(ndxy, dss));
            const u64 c02 = f2fma(dxy, dys, f2mul(ndxs, dyy));
            const u64 c11 = f2fma(dxx, dss, f2mul(ndxs, dxs));
            const u64 c12 = f2fma(dxy, dxs, f2mul(ndys, dxx));
            const u64 c22 = f2fma(dxx, dyy, f2mul(ndxy, dxy));
            const u64 det = f2fma(dxx, c00, f2fma(dxy, c01, f2mul(dxs, c02)));

            float det0, det1;  upk2(det, det0, det1);
            const bool ok0 = nms0 && (det0 != 0.0f);
            const bool ok1 = nms1 && (det1 != 0.0f);
            const float inv0 = __fdividef(1.0f, (det0 == 0.0f) ? 1.0f : det0);
            const float inv1 = __fdividef(1.0f, (det1 == 0.0f) ? 1.0f : det1);
            const u64 inv = pk2(inv0, inv1);

            const u64 u0 = f2mul(f2fma(c00, b0, f2fma(c01, b1, f2mul(c02, b2))), inv);
            const u64 u1 = f2mul(f2fma(c01, b0, f2fma(c11, b1, f2mul(c12, b2))), inv);
            const u64 u2 = f2mul(f2fma(c02, b0, f2fma(c12, b1, f2mul(c22, b2))), inv);
            const u64 bu = f2fma(b0, u0, f2fma(b1, u1, f2mul(b2, u2)));  // b·u

            float u00, u01, u10, u11, u20, u21, bu0, bu1;
            upk2(u0, u00, u01);
            upk2(u1, u10, u11);
            upk2(u2, u20, u21);
            upk2(bu, bu0, bu1);

            // s = ok && max|u| <= 0.7  (if !ok: d=0 anyway; if ok: d=-u)
            const bool s0 = ok0 && (fmaxf(fmaxf(fabsf(u00), fabsf(u10)), fabsf(u20)) <= 0.7f);
            const bool s1 = ok1 && (fmaxf(fmaxf(fabsf(u01), fabsf(u11)), fabsf(u21)) <= 0.7f);

            const float d00 = s0 ? -u00 : 0.0f, d01 = s1 ? -u01 : 0.0f;
            const float d10 = s0 ? -u10 : 0.0f, d11 = s1 ? -u11 : 0.0f;
            const float d20 = s0 ? -u20 : 0.0f, d21 = s1 ? -u21 : 0.0f;
            const float e0  = s0 ? -0.5f * bu0 : 0.0f;
            const float e1  = s1 ? -0.5f * bu1 : 0.0f;

            if (active) {
                oc0[o0 + 0*DHW] = df0 + d20;  oc0[o1 + 0*DHW] = df1 + d21;
                oc0[o0 + 1*DHW] = wf  + d00;  oc0[o1 + 1*DHW] = wf  + d01;
                oc0[o0 + 2*DHW] = hf  + d10;  oc0[o1 + 2*DHW] = hf  + d11;
                oy [o0] = xc0 + e0 + (ok0 ? BONUS : 0.0f);
                oy [o1] = xc1 + e1 + (ok1 ? BONUS : 0.0f);
            }
        }
        obase += WD;
    }
    #undef LOADROW
    #undef COMMIT
}

__global__ __launch_bounds__(128, 8)
void cqi_kernel(const float* __restrict__ xg, float* __restrict__ out)
{
    const int gw   = blockIdx.x * WPB + (threadIdx.x >> 5);
    const int lane = threadIdx.x & 31;
    if (gw < HALF_TASKS)
        run_half<0>(xg, out, gw, lane);
    else
        run_half<1>(xg, out, gw - HALF_TASKS, lane);
}

extern "C" void kernel_launch(void* const* d_in, const int* in_sizes, int n_in,
                              void* d_out, int out_size)
{
    const float* x = (const float*)d_in[0];
    float* out = (float*)d_out;
    dim3 block(WPB * 32, 1, 1);
    dim3 grid(NTASK / WPB, 1, 1);
    cqi_kernel<<<grid, block>>>(x, out);
}

// round 11
// speedup vs baseline: 1.0635x; 1.0635x over previous
#include <cuda_runtime.h>

// x: (2,8,4,256,384) fp32 -> 16 independent DxHxW volumes
#define WD   384
#define HT   256
#define DP   4
#define HW   (HT*WD)          // 98304
#define DHW  (DP*HW)          // 393216
#define NIMG 16

#define OUTW   30             // output columns per warp strip (lanes 1..30)
#define NSTRIP 13             // ceil(384/30)
#define CH     8              // output rows per h-chunk
#define NCH    (HT/CH)        // 32
#define WPB    4              // warps per block
#define NTASK  (NSTRIP*NCH*NIMG)   // 6656 warps

#define BONUS 10.0f
#define FULL  0xffffffffu

__global__ __launch_bounds__(128, 6)
void cqi_kernel(const float* __restrict__ xg, float* __restrict__ out)
{
    const int gw   = blockIdx.x * WPB + (threadIdx.x >> 5);
    const int lane = threadIdx.x & 31;

    const int img   = gw / (NSTRIP * NCH);
    const int rem   = gw - img * (NSTRIP * NCH);
    const int strip = rem % NSTRIP;
    const int hc    = rem / NSTRIP;

    const int w0   = strip * OUTW;
    const int wout = w0 + lane - 1;                 // this lane's output w
    const bool active = (lane >= 1) && (lane <= 30) && (wout < WD);
    int wcol = wout; if (wcol < 0) wcol = 0; if (wcol > WD-1) wcol = WD-1;

    const int h0 = hc * CH;
    const float wf = (float)wout;

    const float* __restrict__ xin = xg + (size_t)img * DHW + wcol;

    // 3-slot rolling row window, slot selected by compile-time (i+k)%3:
    float val[3][4], lf[3][4], rg[3][4], wm[3][4];
    float pend[4];                                  // raw prefetch of next row

    #define LOADROW(HR, DST)                                             \
        do {                                                             \
            const float* _p = xin + (HR) * WD;                           \
            (DST)[0] = __ldg(_p);                                        \
            (DST)[1] = __ldg(_p + HW);                                   \
            (DST)[2] = __ldg(_p + 2*HW);                                 \
            (DST)[3] = __ldg(_p + 3*HW);                                 \
        } while (0)

    // from raw[4] into slot S: shifted copies via shfl; NMS w-max via fmax only
    #define COMMIT(RAW, S)                                               \
        do {                                                             \
            _Pragma("unroll")                                            \
            for (int p = 0; p < 4; ++p) {                                \
                float _v = (RAW)[p];                                     \
                val[S][p] = _v;                                          \
                lf[S][p]  = __shfl_up_sync(FULL, _v, 1);                 \
                rg[S][p]  = __shfl_down_sync(FULL, _v, 1);               \
            }                                                            \
            float _h0 = fmaxf(fmaxf(lf[S][0], val[S][0]), rg[S][0]);     \
            float _h1 = fmaxf(fmaxf(lf[S][1], val[S][1]), rg[S][1]);     \
            float _h2 = fmaxf(fmaxf(lf[S][2], val[S][2]), rg[S][2]);     \
            float _h3 = fmaxf(fmaxf(lf[S][3], val[S][3]), rg[S][3]);     \
            float _m01 = fmaxf(_h0, _h1);                                \
            float _m12 = fmaxf(_h1, _h2);                                \
            float _m23 = fmaxf(_h2, _h3);                                \
            wm[S][0] = _m01;                                             \
            wm[S][1] = fmaxf(_m01, _h2);                                 \
            wm[S][2] = fmaxf(_m12, _h3);                                 \
            wm[S][3] = _m23;                                             \
        } while (0)

    // ---- prologue: rows h0-1 (slot 0) and h0 (slot 1) ----
    {
        float ra[4], rb[4];
        int r_up = h0 - 1; if (r_up < 0) r_up = 0;
        LOADROW(r_up, ra);
        LOADROW(h0,  rb);
        COMMIT(ra, 0);
        COMMIT(rb, 1);
        int r_dn = h0 + 1; if (r_dn > HT-1) r_dn = HT-1;
        LOADROW(r_dn, pend);
    }

    float* __restrict__ oc0 = out + (size_t)img * 3 * DHW;
    float* __restrict__ oy  = out + (size_t)NIMG * 3 * DHW + (size_t)img * DHW;

    const int PA[4] = {0, 0, 1, 2};    // clamped plane d-1
    const int PC[4] = {1, 2, 3, 3};    // clamped plane d+1

    int obase = h0 * WD + wout;

    #pragma unroll
    for (int i = 0; i < CH; ++i) {
        const int h  = h0 + i;
        const int sU = i % 3;           // row h-1
        const int sM = (i + 1) % 3;     // row h
        const int sD = (i + 2) % 3;     // row h+1 (written now)
        const float hf = (float)h;

        // consume prefetch into slot sD, issue next prefetch (row h+2, clamped)
        float tmp[4];
        #pragma unroll
        for (int p = 0; p < 4; ++p) tmp[p] = pend[p];
        int rn = h + 2; if (rn > HT-1) rn = HT-1;
        LOADROW(rn, pend);
        COMMIT(tmp, sD);

        #pragma unroll
        for (int d = 0; d < DP; ++d) {
            const int pa = PA[d], pc = PC[d];
            const float df = (float)d;

            const float xc = val[sM][d];
            const float mx = fmaxf(fmaxf(wm[sU][d], wm[sM][d]), wm[sD][d]);
            const bool nms = (xc == mx);
            const int o = obase + d * HW;

            // warp-uniform fast path: no NMS max among output lanes ->
            // every lane writes trivial coords and y = xc (bit-exact).
            const unsigned bal = __ballot_sync(FULL, nms && active);
            if (bal == 0u) {
                if (active) {
                    oc0[o + 0*DHW] = df;
                    oc0[o + 1*DHW] = wf;
                    oc0[o + 2*DHW] = hf;
                    oy [o]         = xc;
                }
                continue;
            }

            const float b0 = 0.5f * (rg[sM][d] - lf[sM][d]);       // dx
            const float b1 = 0.5f * (val[sD][d] - val[sU][d]);     // dy
            const float b2 = 0.5f * (val[sM][pa] - val[sM][pc]);   // ds (flipped)

            const float dxx = rg[sM][d]   - 2.0f*xc + lf[sM][d];
            const float dyy = val[sD][d]  - 2.0f*xc + val[sU][d];
            const float dss = val[sM][pc] - 2.0f*xc + val[sM][pa];
            const float dxy = 0.25f * ( lf[sU][d] - rg[sU][d] - lf[sD][d] + rg[sD][d]);
            const float dys = 0.25f * (-val[sU][pa] + val[sD][pa] + val[sU][pc] - val[sD][pc]);
            const float dxs = 0.25f * (-lf[sM][pa] + rg[sM][pa] + lf[sM][pc] - rg[sM][pc]);

            const float c00 = dyy*dss - dys*dys;
            const float c01 = dxs*dys - dxy*dss;
            const float c02 = dxy*dys - dxs*dyy;
            const float c11 = dxx*dss - dxs*dxs;
            const float c12 = dxy*dxs - dxx*dys;
            const float c22 = dxx*dyy - dxy*dxy;
            const float det = dxx*c00 + dxy*c01 + dxs*c02;

            const bool ok = nms && (det != 0.0f);
            const float invdet = __fdividef(1.0f, (det == 0.0f) ? 1.0f : det);

            const float u0 = (c00*b0 + c01*b1 + c02*b2) * invdet;
            const float u1 = (c01*b0 + c11*b1 + c12*b2) * invdet;
            const float u2 = (c02*b0 + c12*b1 + c22*b2) * invdet;

            float d0 = ok ? -u0 : 0.0f;
            float d1 = ok ? -u1 : 0.0f;
            float d2 = ok ? -u2 : 0.0f;

            const bool small = fmaxf(fmaxf(fabsf(d0), fabsf(d1)), fabsf(d2)) <= 0.7f;
            d0 = small ? d0 : 0.0f;
            d1 = small ? d1 : 0.0f;
            d2 = small ? d2 : 0.0f;

            const float dE = 0.5f * (b0*d0 + b1*d1 + b2*d2);

            if (active) {
                oc0[o + 0*DHW] = df + d2;
                oc0[o + 1*DHW] = wf + d0;
                oc0[o + 2*DHW] = hf + d1;
                oy [o]         = xc + dE + (ok ? BONUS : 0.0f);
            }
        }
        obase += WD;
    }
    #undef LOADROW
    #undef COMMIT
}

extern "C" void kernel_launch(void* const* d_in, const int* in_sizes, int n_in,
                              void* d_out, int out_size)
{
    const float* x = (const float*)d_in[0];
    float* out = (float*)d_out;
    dim3 block(WPB * 32, 1, 1);
    dim3 grid(NTASK / WPB, 1, 1);
    cqi_kernel<<<grid, block>>>(x, out);
}